// round 1
// baseline (speedup 1.0000x reference)
#include <cuda_runtime.h>
#include <math.h>

// ---------------- problem constants ----------------
#define B_  16
#define N_  1024
#define D_  64
#define EPS_ 0.1f
#define TOTAL_ROWS (B_*N_)        // 16384
#define NBLK 148
#define NTHR 1024

// ---------------- device scratch (static, no allocs) ----------------
__device__ float g_sx[B_*N_*D_];          // softmax(x)   4MB
__device__ float g_sy[B_*N_*D_];          // softmax(y)   4MB
__device__ float g_x2[TOTAL_ROWS];        // ||sx_i||^2
__device__ float g_y2[TOTAL_ROWS];        // ||sy_j||^2
__device__ float g_C[B_*N_*N_];           // cost matrix  64MB
__device__ float g_K[B_*N_*N_];           // exp(-C/eps)  64MB
__device__ float g_a[TOTAL_ROWS];         // exp(u/eps)
__device__ float g_b[TOTAL_ROWS];         // exp(v/eps)
__device__ float g_du[TOTAL_ROWS];        // |delta u| per row / partials
__device__ unsigned g_count;              // barrier arrive count
__device__ unsigned g_gen;                // barrier generation
__device__ int g_stop;                    // convergence flag

// ---------------- softmax + row norms ----------------
// one warp per row (64 elems -> 2 per lane); rows [0,16384) = x, [16384,32768) = y
__global__ __launch_bounds__(256) void softmax_kernel(const float* __restrict__ x,
                                                      const float* __restrict__ y) {
    int w    = (blockIdx.x * blockDim.x + threadIdx.x) >> 5;
    int lane = threadIdx.x & 31;
    if (w >= 2 * TOTAL_ROWS) return;
    const float* src; float* dst; float* nrm; int r;
    if (w < TOTAL_ROWS) { src = x; dst = g_sx; nrm = g_x2; r = w; }
    else                { src = y; dst = g_sy; nrm = g_y2; r = w - TOTAL_ROWS; }
    const float* p = src + (size_t)r * D_;
    float v0 = p[lane], v1 = p[lane + 32];
    float m = fmaxf(v0, v1);
    #pragma unroll
    for (int o = 16; o; o >>= 1) m = fmaxf(m, __shfl_xor_sync(0xffffffffu, m, o));
    float e0 = expf(v0 - m), e1 = expf(v1 - m);
    float s = e0 + e1;
    #pragma unroll
    for (int o = 16; o; o >>= 1) s += __shfl_xor_sync(0xffffffffu, s, o);
    float inv = 1.0f / s;
    float p0 = e0 * inv, p1 = e1 * inv;
    dst[(size_t)r * D_ + lane]      = p0;
    dst[(size_t)r * D_ + lane + 32] = p1;
    float n = p0 * p0 + p1 * p1;
    #pragma unroll
    for (int o = 16; o; o >>= 1) n += __shfl_xor_sync(0xffffffffu, n, o);
    if (lane == 0) nrm[r] = n;
}

// ---------------- cost + kernel matrix: C = x2 + y2 - 2 x.y ; K = exp(-C/eps) ----
// 64x64 output tile per block, full K(=D)=64. Transposed smem tiles -> conflict-free.
__global__ __launch_bounds__(256) void cost_kernel() {
    __shared__ float xsT[64][65];
    __shared__ float ysT[64][65];
    int b  = blockIdx.z;
    int i0 = blockIdx.y << 6;
    int j0 = blockIdx.x << 6;
    int tid = threadIdx.x;
    const float* xb = g_sx + (size_t)b * N_ * D_;
    const float* yb = g_sy + (size_t)b * N_ * D_;
    for (int idx = tid; idx < 64 * 64; idx += 256) {
        int i = idx >> 6, d = idx & 63;
        xsT[d][i] = xb[(size_t)(i0 + i) * D_ + d];
        ysT[d][i] = yb[(size_t)(j0 + i) * D_ + d];
    }
    __syncthreads();
    int tx = tid & 31, ty = tid >> 5;   // ty in 0..7
    float acc[8][2];
    #pragma unroll
    for (int a = 0; a < 8; a++) { acc[a][0] = 0.f; acc[a][1] = 0.f; }
    #pragma unroll 8
    for (int d = 0; d < 64; d++) {
        float y0 = ysT[d][tx], y1 = ysT[d][tx + 32];
        #pragma unroll
        for (int a = 0; a < 8; a++) {
            float xv = xsT[d][ty + (a << 3)];
            acc[a][0] = fmaf(xv, y0, acc[a][0]);
            acc[a][1] = fmaf(xv, y1, acc[a][1]);
        }
    }
    #pragma unroll
    for (int a = 0; a < 8; a++) {
        int i = i0 + ty + (a << 3);
        float xi2 = g_x2[(b << 10) + i];
        size_t base = ((size_t)((b << 10) + i)) << 10;
        #pragma unroll
        for (int q = 0; q < 2; q++) {
            int j = j0 + tx + (q << 5);
            float c = xi2 + g_y2[(b << 10) + j] - 2.0f * acc[a][q];
            g_C[base + j] = c;
            g_K[base + j] = expf(-c * (1.0f / EPS_));
        }
    }
}

// ---------------- software grid barrier (sense via generation counter) ----------
__device__ __forceinline__ void grid_sync() {
    __syncthreads();
    if (threadIdx.x == 0) {
        unsigned gen = *((volatile unsigned*)&g_gen);   // read BEFORE arrive
        __threadfence();                                // release my writes
        unsigned t = atomicAdd(&g_count, 1u);
        if (t == gridDim.x - 1) {
            atomicExch(&g_count, 0u);
            __threadfence();
            atomicAdd(&g_gen, 1u);
        } else {
            while (*((volatile unsigned*)&g_gen) == gen) __nanosleep(64);
        }
        __threadfence();                                // acquire others' writes
    }
    __syncthreads();
}

// ---------------- persistent Sinkhorn loop + final cost ----------------
__global__ __launch_bounds__(NTHR, 1) void sinkhorn_kernel(float* __restrict__ out) {
    __shared__ float sbuf[2048];
    const int tid = threadIdx.x, blk = blockIdx.x;
    const int lane = tid & 31, warp = tid >> 5;
    const float mu_eff = 1.0f / 1024.0f + 1e-8f;
    const float log_mu = logf(mu_eff);

    // init a=b=1, clear stop flag
    {
        int g = blk * NTHR + tid;
        if (g < TOTAL_ROWS) { g_a[g] = 1.0f; g_b[g] = 1.0f; }
        if (blk == 0 && tid == 0) g_stop = 0;
    }
    grid_sync();

    const int chunk = (TOTAL_ROWS + NBLK - 1) / NBLK;   // 111 rows/block
    const int rs = blk * chunk;
    const int re = min(rs + chunk, TOTAL_ROWS);

    for (int it = 0; it < 100; ++it) {
        // ---- row pass: s_i = sum_j K_ij b_j ; update a, |du| ----
        if (rs < re) {
            int b0 = rs >> 10;
            int nstage = (((re - 1) >> 10) - b0 + 1) << 10;   // 1024 or 2048
            for (int idx = tid; idx < nstage; idx += NTHR)
                sbuf[idx] = __ldcg(&g_b[(b0 << 10) + idx]);
            __syncthreads();
            for (int r = rs + warp; r < re; r += 32) {
                const float* bs = &sbuf[((r >> 10) - b0) << 10];
                const float* Kr = g_K + ((size_t)r << 10);
                float acc = 0.f;
                #pragma unroll
                for (int k = 0; k < 32; k++)
                    acc = fmaf(Kr[lane + (k << 5)], bs[lane + (k << 5)], acc);
                #pragma unroll
                for (int o = 16; o; o >>= 1) acc += __shfl_xor_sync(0xffffffffu, acc, o);
                if (lane == 0) {
                    float aold = __ldcg(&g_a[r]);
                    float as = fmaf(aold, acc, 1e-6f);        // a*s + 1e-6
                    float du = EPS_ * (log_mu - logf(as));
                    __stcg(&g_a[r], mu_eff * aold / as);
                    __stcg(&g_du[r], fabsf(du));
                }
            }
        }
        grid_sync();
        // ---- col pass: t_j = sum_i K_ij a_i ; update b.  err on block 128. ----
        if (blk < 128) {
            int bb = blk >> 3;
            int j0 = (blk & 7) << 7;
            sbuf[tid] = __ldcg(&g_a[(bb << 10) + tid]);       // stage a[batch]
            __syncthreads();
            int c = tid & 127, ir = tid >> 7;                 // 128 cols x 8 i-groups
            const float* Kb = g_K + ((size_t)bb << 20) + j0 + c;
            float acc = 0.f;
            #pragma unroll 4
            for (int i = ir; i < 1024; i += 8)
                acc = fmaf(Kb[(size_t)i << 10], sbuf[i], acc);
            __syncthreads();
            sbuf[1024 + tid] = acc;
            __syncthreads();
            if (tid < 128) {
                float t = 0.f;
                #pragma unroll
                for (int g = 0; g < 8; g++) t += sbuf[1024 + (g << 7) + tid];
                int j = (bb << 10) + j0 + tid;
                float bold = __ldcg(&g_b[j]);
                float bt = fmaf(bold, t, 1e-6f);
                __stcg(&g_b[j], mu_eff * bold / bt);
            }
        } else if (blk == 128) {
            // err = mean_b sum_i |du| = total/16, deterministic fixed-order reduce
            float s = 0.f;
            #pragma unroll
            for (int k = 0; k < 16; k++) s += __ldcg(&g_du[tid + (k << 10)]);
            sbuf[tid] = s;
            __syncthreads();
            for (int off = 512; off; off >>= 1) {
                if (tid < off) sbuf[tid] += sbuf[tid + off];
                __syncthreads();
            }
            if (tid == 0) {
                float err = sbuf[0] * (1.0f / 16.0f);
                g_stop = (err < 0.1f) ? 1 : 0;
                __threadfence();
            }
        }
        grid_sync();
        if (*((volatile int*)&g_stop)) break;
    }

    // ---- final: cost_b = sum_ij a_i K_ij b_j C_ij ; out = mean_b ----
    if (rs < re) {
        int b0 = rs >> 10;
        int nstage = (((re - 1) >> 10) - b0 + 1) << 10;
        __syncthreads();
        for (int idx = tid; idx < nstage; idx += NTHR)
            sbuf[idx] = __ldcg(&g_b[(b0 << 10) + idx]);
        __syncthreads();
        for (int r = rs + warp; r < re; r += 32) {
            const float* bs = &sbuf[((r >> 10) - b0) << 10];
            const float* Kr = g_K + ((size_t)r << 10);
            const float* Cr = g_C + ((size_t)r << 10);
            float acc = 0.f;
            #pragma unroll 8
            for (int k = 0; k < 32; k++) {
                int o = lane + (k << 5);
                acc = fmaf(Kr[o] * Cr[o], bs[o], acc);
            }
            #pragma unroll
            for (int o = 16; o; o >>= 1) acc += __shfl_xor_sync(0xffffffffu, acc, o);
            if (lane == 0)
                __stcg(&g_du[r], __ldcg(&g_a[r]) * acc);
        }
    }
    grid_sync();
    if (blk == 0) {
        float s = 0.f;
        #pragma unroll
        for (int k = 0; k < 16; k++) s += __ldcg(&g_du[tid + (k << 10)]);
        sbuf[tid] = s;
        __syncthreads();
        for (int off = 512; off; off >>= 1) {
            if (tid < off) sbuf[tid] += sbuf[tid + off];
            __syncthreads();
        }
        if (tid == 0) out[0] = sbuf[0] * (1.0f / 16.0f);
    }
}

// ---------------- launch ----------------
extern "C" void kernel_launch(void* const* d_in, const int* in_sizes, int n_in,
                              void* d_out, int out_size) {
    const float* x = (const float*)d_in[0];
    const float* y = (const float*)d_in[1];
    (void)in_sizes; (void)n_in; (void)out_size;

    softmax_kernel<<<(2 * TOTAL_ROWS) / 8, 256>>>(x, y);      // 32768 warps, 8/block
    dim3 gc(16, 16, 16);                                       // (j-tiles, i-tiles, batch)
    cost_kernel<<<gc, 256>>>();
    sinkhorn_kernel<<<NBLK, NTHR>>>((float*)d_out);
}

// round 4
// speedup vs baseline: 2.5681x; 2.5681x over previous
#include <cuda_runtime.h>
#include <cuda_fp16.h>
#include <math.h>
#include <stdint.h>

// ---------------- problem constants ----------------
#define B_  16
#define N_  1024
#define D_  64
#define EPS_ 0.1f
#define TOTAL_ROWS (B_*N_)        // 16384
#define NBLK 148
#define NTHR 1024

// ---------------- device scratch (static, no allocs) ----------------
__device__ __half g_sxh[TOTAL_ROWS*D_];   // softmax(x) fp16  2MB
__device__ __half g_syh[TOTAL_ROWS*D_];   // softmax(y) fp16  2MB
__device__ float  g_x2[TOTAL_ROWS];       // ||sx_i||^2 (fp32)
__device__ float  g_y2[TOTAL_ROWS];       // ||sy_j||^2 (fp32)
__device__ __half g_Kh[(size_t)B_*N_*N_]; // K = exp(-C/eps), fp16, 32MB
__device__ float  g_a[TOTAL_ROWS];
__device__ float  g_b[TOTAL_ROWS];
__device__ float  g_du[TOTAL_ROWS];
__device__ unsigned g_count;
__device__ unsigned g_gen;
__device__ int g_stop;

// ---------------- helpers ----------------
__device__ __forceinline__ uint32_t smem_u32(const void* p) {
    uint32_t a;
    asm("{ .reg .u64 t; cvta.to.shared.u64 t, %1; cvt.u32.u64 %0, t; }" : "=r"(a) : "l"(p));
    return a;
}
__device__ __forceinline__ void ldsm_x4(uint32_t& r0, uint32_t& r1, uint32_t& r2, uint32_t& r3,
                                        uint32_t addr) {
    asm volatile("ldmatrix.sync.aligned.m8n8.x4.shared.b16 {%0,%1,%2,%3}, [%4];"
                 : "=r"(r0), "=r"(r1), "=r"(r2), "=r"(r3) : "r"(addr));
}
__device__ __forceinline__ void mma16816(float* c, const uint32_t* a, const uint32_t* b) {
    asm volatile(
        "mma.sync.aligned.m16n8k16.row.col.f32.f16.f16.f32 "
        "{%0,%1,%2,%3}, {%4,%5,%6,%7}, {%8,%9}, {%0,%1,%2,%3};"
        : "+f"(c[0]), "+f"(c[1]), "+f"(c[2]), "+f"(c[3])
        : "r"(a[0]), "r"(a[1]), "r"(a[2]), "r"(a[3]), "r"(b[0]), "r"(b[1]));
}

// ---------------- softmax: fp16 outputs + fp32 norms ----------------
__global__ __launch_bounds__(256) void softmax_kernel(const float* __restrict__ x,
                                                      const float* __restrict__ y) {
    int w    = (blockIdx.x * blockDim.x + threadIdx.x) >> 5;
    int lane = threadIdx.x & 31;
    if (w >= 2 * TOTAL_ROWS) return;
    const float* src; __half* dst; float* nrm; int r;
    if (w < TOTAL_ROWS) { src = x; dst = g_sxh; nrm = g_x2; r = w; }
    else                { src = y; dst = g_syh; nrm = g_y2; r = w - TOTAL_ROWS; }
    float2 v = ((const float2*)(src + (size_t)r * D_))[lane];
    float m = fmaxf(v.x, v.y);
    #pragma unroll
    for (int o = 16; o; o >>= 1) m = fmaxf(m, __shfl_xor_sync(0xffffffffu, m, o));
    float e0 = __expf(v.x - m), e1 = __expf(v.y - m);
    float s = e0 + e1;
    #pragma unroll
    for (int o = 16; o; o >>= 1) s += __shfl_xor_sync(0xffffffffu, s, o);
    float inv = 1.0f / s;
    float p0 = e0 * inv, p1 = e1 * inv;
    ((__half2*)dst)[(size_t)r * 32 + lane] = __floats2half2_rn(p0, p1);
    float n = p0 * p0 + p1 * p1;
    #pragma unroll
    for (int o = 16; o; o >>= 1) n += __shfl_xor_sync(0xffffffffu, n, o);
    if (lane == 0) nrm[r] = n;
}

// ---------------- cost kernel: HMMA mma.sync + fused exp -> fp16 K ----------
// CTA: 256 thr (8 warps, 4x2), tile M=128 x N=64, Kdepth=64.
// Each warp: 32x32 output = 2 m16 x 4 n8 fragments, 4 k16 steps.
__global__ __launch_bounds__(256) void cost_kernel() {
    __shared__ __half As[128][72];   // padded: 144B row stride, conflict-free ldmatrix
    __shared__ __half Bs[64][72];
    __shared__ float  ys2[64];
    const int tid = threadIdx.x, warp = tid >> 5, lane = tid & 31;
    const int jt = blockIdx.x, it = blockIdx.y, b = blockIdx.z;
    const int i_base = (b << 10) + (it << 7);
    const int j_base = (b << 10) + (jt << 6);

    // A: 128 rows x 8 chunks of uint4 (1024), 4 iters
    #pragma unroll
    for (int q = 0; q < 4; q++) {
        int idx = tid + (q << 8);
        int r = idx >> 3, ch = idx & 7;
        *(uint4*)&As[r][ch << 3] = ((const uint4*)(g_sxh + (size_t)(i_base + r) * D_))[ch];
    }
    // B: 64 rows x 8 chunks (512), 2 iters
    #pragma unroll
    for (int q = 0; q < 2; q++) {
        int idx = tid + (q << 8);
        int r = idx >> 3, ch = idx & 7;
        *(uint4*)&Bs[r][ch << 3] = ((const uint4*)(g_syh + (size_t)(j_base + r) * D_))[ch];
    }
    if (tid < 64) ys2[tid] = g_y2[j_base + tid];
    __syncthreads();

    const int wr = warp & 3, wc = warp >> 2;
    const int m0 = wr << 5, n0 = wc << 5;

    float acc[2][4][4];
    #pragma unroll
    for (int mt = 0; mt < 2; mt++)
        #pragma unroll
        for (int nt = 0; nt < 4; nt++)
            #pragma unroll
            for (int e = 0; e < 4; e++) acc[mt][nt][e] = 0.f;

    #pragma unroll
    for (int ks = 0; ks < 4; ks++) {
        const int k0 = ks << 4;
        uint32_t af[2][4], bf[4][2];
        // A fragments: rows m0+mt*16+(lane&15), col k0 + (lane>>4)*8
        #pragma unroll
        for (int mt = 0; mt < 2; mt++) {
            uint32_t addr = smem_u32(&As[m0 + (mt << 4) + (lane & 15)][k0 + ((lane >> 4) << 3)]);
            ldsm_x4(af[mt][0], af[mt][1], af[mt][2], af[mt][3], addr);
        }
        // B fragments: 2 x4-loads cover 4 n8 tiles
        #pragma unroll
        for (int np = 0; np < 2; np++) {
            int mat = lane >> 3, rin = lane & 7;
            int row = n0 + (np << 4) + ((mat >> 1) << 3) + rin;
            int col = k0 + ((mat & 1) << 3);
            uint32_t addr = smem_u32(&Bs[row][col]);
            uint32_t r0, r1, r2, r3;
            ldsm_x4(r0, r1, r2, r3, addr);
            bf[np * 2][0] = r0; bf[np * 2][1] = r1;
            bf[np * 2 + 1][0] = r2; bf[np * 2 + 1][1] = r3;
        }
        #pragma unroll
        for (int mt = 0; mt < 2; mt++)
            #pragma unroll
            for (int nt = 0; nt < 4; nt++)
                mma16816(acc[mt][nt], af[mt], bf[nt]);
    }

    // epilogue: C = x2 + y2 - 2s ; K = exp(-10 C) -> fp16
    const int g = lane >> 2, tq = lane & 3;
    #pragma unroll
    for (int mt = 0; mt < 2; mt++) {
        int gi0 = i_base + m0 + (mt << 4) + g;
        int gi1 = gi0 + 8;
        float xi0 = g_x2[gi0], xi1 = g_x2[gi1];
        __half* d0 = g_Kh + ((size_t)gi0 << 10) + (jt << 6);
        __half* d1 = g_Kh + ((size_t)gi1 << 10) + (jt << 6);
        #pragma unroll
        for (int nt = 0; nt < 4; nt++) {
            int jl = n0 + (nt << 3) + (tq << 1);
            float yj0 = ys2[jl], yj1 = ys2[jl + 1];
            float c00 = xi0 + yj0 - 2.0f * acc[mt][nt][0];
            float c01 = xi0 + yj1 - 2.0f * acc[mt][nt][1];
            float c10 = xi1 + yj0 - 2.0f * acc[mt][nt][2];
            float c11 = xi1 + yj1 - 2.0f * acc[mt][nt][3];
            __half2 h0 = __floats2half2_rn(__expf(-10.0f * c00), __expf(-10.0f * c01));
            __half2 h1 = __floats2half2_rn(__expf(-10.0f * c10), __expf(-10.0f * c11));
            *(__half2*)(d0 + jl) = h0;
            *(__half2*)(d1 + jl) = h1;
        }
    }
}

// ---------------- software grid barrier ----------------
__device__ __forceinline__ void grid_sync() {
    __syncthreads();
    if (threadIdx.x == 0) {
        unsigned gen = *((volatile unsigned*)&g_gen);
        __threadfence();
        unsigned t = atomicAdd(&g_count, 1u);
        if (t == gridDim.x - 1) {
            atomicExch(&g_count, 0u);
            __threadfence();
            atomicAdd(&g_gen, 1u);
        } else {
            while (*((volatile unsigned*)&g_gen) == gen) __nanosleep(32);
        }
        __threadfence();
    }
    __syncthreads();
}

// ---------------- persistent Sinkhorn loop + final cost ----------------
__global__ __launch_bounds__(NTHR, 1) void sinkhorn_kernel(float* __restrict__ out) {
    __shared__ __align__(16) float sbuf[9216];
    const int tid = threadIdx.x, blk = blockIdx.x;
    const int lane = tid & 31, warp = tid >> 5;
    const float mu = 1.0f / 1024.0f + 1e-8f;
    const float log_mu = logf(mu);

    {
        int g = blk * NTHR + tid;
        if (g < TOTAL_ROWS) { g_a[g] = 1.0f; g_b[g] = 1.0f; }
        if (blk == 0 && tid == 0) g_stop = 0;
    }
    grid_sync();

    const int chunk = (TOTAL_ROWS + NBLK - 1) / NBLK;   // 111
    const int rs = blk * chunk;
    const int re = min(rs + chunk, TOTAL_ROWS);
    const int b0 = rs >> 10;
    const int nstage = (rs < re) ? ((((re - 1) >> 10) - b0 + 1) << 10) : 0;

    for (int it = 0; it < 100; ++it) {
        // ---- row pass: s_i = sum_j K_ij b_j ; update a, |du| ----
        if (rs < re) {
            for (int idx = tid; idx < nstage; idx += NTHR)
                sbuf[idx] = __ldcg(&g_b[(b0 << 10) + idx]);
            __syncthreads();
            for (int r = rs + warp; r < re; r += 32) {
                const float* bs = sbuf + (((r >> 10) - b0) << 10);
                const uint4* Kr = (const uint4*)(g_Kh + ((size_t)r << 10));
                float acc = 0.f;
                #pragma unroll
                for (int k = 0; k < 4; k++) {
                    int u = lane + (k << 5);
                    uint4 v = Kr[u];
                    const float4* bp = (const float4*)(bs + (u << 3));
                    float4 q0 = bp[0], q1 = bp[1];
                    float2 f0 = __half22float2(*(__half2*)&v.x);
                    float2 f1 = __half22float2(*(__half2*)&v.y);
                    float2 f2 = __half22float2(*(__half2*)&v.z);
                    float2 f3 = __half22float2(*(__half2*)&v.w);
                    acc = fmaf(f0.x, q0.x, fmaf(f0.y, q0.y, fmaf(f1.x, q0.z, fmaf(f1.y, q0.w, acc))));
                    acc = fmaf(f2.x, q1.x, fmaf(f2.y, q1.y, fmaf(f3.x, q1.z, fmaf(f3.y, q1.w, acc))));
                }
                #pragma unroll
                for (int o = 16; o; o >>= 1) acc += __shfl_xor_sync(0xffffffffu, acc, o);
                if (lane == 0) {
                    float aold = __ldcg(&g_a[r]);
                    float as = fmaf(aold, acc, 1e-6f);
                    float du = EPS_ * (log_mu - __logf(as));
                    __stcg(&g_a[r], mu * aold / as);
                    __stcg(&g_du[r], fabsf(du));
                }
            }
        }
        grid_sync();
        // ---- col pass (blocks 0..127): t_j = sum_i K_ij a_i ; update b ----
        if (blk < 128) {
            int bb = blk >> 3, j0 = (blk & 7) << 7;
            sbuf[tid] = __ldcg(&g_a[(bb << 10) + tid]);
            __syncthreads();
            int jc = tid & 15, ig = tid >> 4;
            float acc[8] = {0.f,0.f,0.f,0.f,0.f,0.f,0.f,0.f};
            const uint4* base = (const uint4*)(g_Kh + ((size_t)bb << 20)) + (j0 >> 3) + jc;
            #pragma unroll 4
            for (int i = ig; i < 1024; i += 64) {
                uint4 v = base[(size_t)i << 7];
                float ai = sbuf[i];
                float2 f0 = __half22float2(*(__half2*)&v.x);
                float2 f1 = __half22float2(*(__half2*)&v.y);
                float2 f2 = __half22float2(*(__half2*)&v.z);
                float2 f3 = __half22float2(*(__half2*)&v.w);
                acc[0] = fmaf(f0.x, ai, acc[0]); acc[1] = fmaf(f0.y, ai, acc[1]);
                acc[2] = fmaf(f1.x, ai, acc[2]); acc[3] = fmaf(f1.y, ai, acc[3]);
                acc[4] = fmaf(f2.x, ai, acc[4]); acc[5] = fmaf(f2.y, ai, acc[5]);
                acc[6] = fmaf(f3.x, ai, acc[6]); acc[7] = fmaf(f3.y, ai, acc[7]);
            }
            float* sred = sbuf + 1024;
            *(float4*)(sred + (ig << 7) + (jc << 3))     = make_float4(acc[0], acc[1], acc[2], acc[3]);
            *(float4*)(sred + (ig << 7) + (jc << 3) + 4) = make_float4(acc[4], acc[5], acc[6], acc[7]);
            __syncthreads();
            if (tid < 128) {
                float t = 0.f;
                #pragma unroll
                for (int g = 0; g < 64; g++) t += sred[(g << 7) + tid];
                int j = (bb << 10) + j0 + tid;
                float bold = __ldcg(&g_b[j]);
                float bt = fmaf(bold, t, 1e-6f);
                __stcg(&g_b[j], mu * bold / bt);
            }
        } else if (blk == 128) {
            float s = 0.f;
            #pragma unroll
            for (int k = 0; k < 16; k++) s += __ldcg(&g_du[tid + (k << 10)]);
            sbuf[tid] = s;
            __syncthreads();
            for (int off = 512; off; off >>= 1) {
                if (tid < off) sbuf[tid] += sbuf[tid + off];
                __syncthreads();
            }
            if (tid == 0) g_stop = (sbuf[0] * (1.0f / 16.0f) < 0.1f) ? 1 : 0;
        }
        grid_sync();
        if (*((volatile int*)&g_stop)) break;
    }

    // ---- final: cost = -eps/16 * sum_r a_r * sum_j (K ln K) b_j ----
    if (rs < re) {
        for (int idx = tid; idx < nstage; idx += NTHR)
            sbuf[idx] = __ldcg(&g_b[(b0 << 10) + idx]);
        __syncthreads();
        for (int r = rs + warp; r < re; r += 32) {
            const float* bs = sbuf + (((r >> 10) - b0) << 10);
            const uint4* Kr = (const uint4*)(g_Kh + ((size_t)r << 10));
            float acc = 0.f;
            #pragma unroll
            for (int k = 0; k < 4; k++) {
                int u = lane + (k << 5);
                uint4 v = Kr[u];
                const float4* bp = (const float4*)(bs + (u << 3));
                float4 q0 = bp[0], q1 = bp[1];
                float2 f0 = __half22float2(*(__half2*)&v.x);
                float2 f1 = __half22float2(*(__half2*)&v.y);
                float2 f2 = __half22float2(*(__half2*)&v.z);
                float2 f3 = __half22float2(*(__half2*)&v.w);
                float t0 = (f0.x > 0.f) ? f0.x * __logf(f0.x) : 0.f;
                float t1 = (f0.y > 0.f) ? f0.y * __logf(f0.y) : 0.f;
                float t2 = (f1.x > 0.f) ? f1.x * __logf(f1.x) : 0.f;
                float t3 = (f1.y > 0.f) ? f1.y * __logf(f1.y) : 0.f;
                float t4 = (f2.x > 0.f) ? f2.x * __logf(f2.x) : 0.f;
                float t5 = (f2.y > 0.f) ? f2.y * __logf(f2.y) : 0.f;
                float t6 = (f3.x > 0.f) ? f3.x * __logf(f3.x) : 0.f;
                float t7 = (f3.y > 0.f) ? f3.y * __logf(f3.y) : 0.f;
                acc = fmaf(t0, q0.x, fmaf(t1, q0.y, fmaf(t2, q0.z, fmaf(t3, q0.w, acc))));
                acc = fmaf(t4, q1.x, fmaf(t5, q1.y, fmaf(t6, q1.z, fmaf(t7, q1.w, acc))));
            }
            #pragma unroll
            for (int o = 16; o; o >>= 1) acc += __shfl_xor_sync(0xffffffffu, acc, o);
            if (lane == 0)
                __stcg(&g_du[r], __ldcg(&g_a[r]) * acc);
        }
    }
    grid_sync();
    if (blk == 0) {
        float s = 0.f;
        #pragma unroll
        for (int k = 0; k < 16; k++) s += __ldcg(&g_du[tid + (k << 10)]);
        sbuf[tid] = s;
        __syncthreads();
        for (int off = 512; off; off >>= 1) {
            if (tid < off) sbuf[tid] += sbuf[tid + off];
            __syncthreads();
        }
        if (tid == 0) out[0] = sbuf[0] * (-EPS_ / 16.0f);
    }
}

// ---------------- launch ----------------
extern "C" void kernel_launch(void* const* d_in, const int* in_sizes, int n_in,
                              void* d_out, int out_size) {
    const float* x = (const float*)d_in[0];
    const float* y = (const float*)d_in[1];
    (void)in_sizes; (void)n_in; (void)out_size;

    softmax_kernel<<<(2 * TOTAL_ROWS) / 8, 256>>>(x, y);
    dim3 gc(16, 8, 16);   // (j-tiles of 64, i-tiles of 128, batch)
    cost_kernel<<<gc, 256>>>();
    sinkhorn_kernel<<<NBLK, NTHR>>>((float*)d_out);
}